// round 3
// baseline (speedup 1.0000x reference)
#include <cuda_runtime.h>

#define B 32
#define N 2048
#define C 64
#define R 32
#define K 64

__device__ float g_vals[B * K];
__device__ int   g_idx[B * K];

// total-order "a before b" in descending-value, ascending-index order
__device__ __forceinline__ bool tfirst(float va, int ia, float vb, int ib) {
    return (va > vb) || (va == vb && ia < ib);
}

// shuffle compare-exchange; partner differs in lane bit j
__device__ __forceinline__ void cmpx(float& v, int& i, int j, bool desc) {
    float ov = __shfl_xor_sync(0xffffffffu, v, j);
    int   oi = __shfl_xor_sync(0xffffffffu, i, j);
    bool lower = ((threadIdx.x & 31 & j) == 0);
    bool mine_first = tfirst(v, i, ov, oi);
    if (mine_first != (lower == desc)) { v = ov; i = oi; }
}

// ---------------------------------------------------------------------------
// Kernel 1: warp-register bitonic top-K. One block per batch row.
// ---------------------------------------------------------------------------
__global__ __launch_bounds__(1024)
void topk_kernel(const float* __restrict__ acc, float* __restrict__ out) {
    __shared__ float sv[N];
    __shared__ int   si[N];
    const int b    = blockIdx.x;
    const int tid  = threadIdx.x;
    const int lane = tid & 31;
    const int w    = tid >> 5;           // warp 0..31

    // ---- load chunk w: elements e0=lane, e1=lane+32 of a 64-elem list ----
    const float* row = acc + b * N;
    float v0 = row[w * 64 + lane];        int i0 = w * 64 + lane;
    float v1 = row[w * 64 + 32 + lane];   int i1 = w * 64 + 32 + lane;

    // ---- bitonic sort 64 elements in-warp (descending, tie: idx asc) ----
    #pragma unroll
    for (int k = 2; k <= 32; k <<= 1) {
        #pragma unroll
        for (int j = k >> 1; j >= 1; j >>= 1) {
            cmpx(v0, i0, j, ((lane)      & k) == 0);
            cmpx(v1, i1, j, ((lane + 32) & k) == 0);
        }
    }
    // k = 64 level: j=32 is a register swap
    if (!tfirst(v0, i0, v1, i1)) {
        float tv = v0; v0 = v1; v1 = tv;
        int   ti = i0; i0 = i1; i1 = ti;
    }
    #pragma unroll
    for (int j = 16; j >= 1; j >>= 1) { cmpx(v0, i0, j, true); cmpx(v1, i1, j, true); }

    sv[w * 64 + lane] = v0;       si[w * 64 + lane] = i0;
    sv[w * 64 + 32 + lane] = v1;  si[w * 64 + 32 + lane] = i1;
    __syncthreads();

    // ---- 5 merge rounds: keep top-64 of pairs of sorted-desc 64-lists ----
    #pragma unroll
    for (int t = 0; t < 5; t++) {
        const int nw = 16 >> t;
        if (w < nw) {
            const int la = 2 * w, lb = 2 * w + 1;
            float a0 = sv[la * 64 + lane];       int a0i = si[la * 64 + lane];
            float a1 = sv[la * 64 + 32 + lane];  int a1i = si[la * 64 + 32 + lane];
            float b0 = sv[lb * 64 + lane];       int b0i = si[lb * 64 + lane];
            float b1 = sv[lb * 64 + 32 + lane];  int b1i = si[lb * 64 + 32 + lane];
            // C[e] = totalmax(A[e], B[63-e])
            float m0 = __shfl_xor_sync(0xffffffffu, b1, 31);
            int  m0i = __shfl_xor_sync(0xffffffffu, b1i, 31);
            float m1 = __shfl_xor_sync(0xffffffffu, b0, 31);
            int  m1i = __shfl_xor_sync(0xffffffffu, b0i, 31);
            if (!tfirst(a0, a0i, m0, m0i)) { a0 = m0; a0i = m0i; }
            if (!tfirst(a1, a1i, m1, m1i)) { a1 = m1; a1i = m1i; }
            // bitonic merge, descending
            if (!tfirst(a0, a0i, a1, a1i)) {
                float tv = a0; a0 = a1; a1 = tv;
                int   ti = a0i; a0i = a1i; a1i = ti;
            }
            #pragma unroll
            for (int j = 16; j >= 1; j >>= 1) { cmpx(a0, a0i, j, true); cmpx(a1, a1i, j, true); }
            sv[w * 64 + lane] = a0;       si[w * 64 + lane] = a0i;
            sv[w * 64 + 32 + lane] = a1;  si[w * 64 + 32 + lane] = a1i;
        }
        __syncthreads();
    }

    if (tid < K) {
        float v  = sv[tid];
        int   id = si[tid];
        out[b * K + tid]         = v;
        out[B * K + b * K + tid] = (float)id;
        g_vals[b * K + tid] = v;
        g_idx [b * K + tid] = id;
    }
}

// ---------------------------------------------------------------------------
// Kernel 2 (after memset of M): frob + scatter of the 64x64 nonzero block.
// grid = (B, 2): y==0 -> frob for batch b; y==1 -> scatter for batch b.
// ---------------------------------------------------------------------------
__global__ __launch_bounds__(1024)
void finalize_kernel(const float* __restrict__ U,
                     float* __restrict__ out,      // base of output
                     float* __restrict__ outM) {   // out + 3*B*K
    __shared__ float s_vals[K];
    __shared__ int   s_idx[K];
    const int b    = blockIdx.x;
    const int tid  = threadIdx.x;

    if (tid < K) { s_vals[tid] = g_vals[b * K + tid]; s_idx[tid] = g_idx[b * K + tid]; }
    __syncthreads();

    if (blockIdx.y == 0) {
        // ---- frob: warp w -> channels {w, w+32}, lane = r ----
        const int lane = tid & 31;
        const int w    = tid >> 5;
        #pragma unroll
        for (int cc = 0; cc < 2; cc++) {
            const int c = w + cc * 32;
            const float* Uc = U + (size_t)c * N * R;
            float au = 0.0f;
            #pragma unroll 8
            for (int k = 0; k < K; k++)
                au = fmaf(s_vals[k], Uc[(size_t)s_idx[k] * R + lane], au);
            float sq = au * au;
            #pragma unroll
            for (int o = 16; o > 0; o >>= 1)
                sq += __shfl_xor_sync(0xffffffffu, sq, o);
            if (lane == 0) out[2 * B * K + b * C + c] = sq / (float)(K * R);
        }
    } else {
        // ---- scatter: M[b, idx_i, idx_j] = v_i * v_j  (4096 pairs, 4/thread)
        float* Mb = outM + (size_t)b * N * N;
        #pragma unroll
        for (int p = tid; p < K * K; p += 1024) {
            const int i = p >> 6, j = p & 63;
            Mb[(size_t)s_idx[i] * N + s_idx[j]] = s_vals[i] * s_vals[j];
        }
    }
}

extern "C" void kernel_launch(void* const* d_in, const int* in_sizes, int n_in,
                              void* d_out, int out_size) {
    const float* acc = (const float*)d_in[0];   // [B, N] float32
    const float* U   = (const float*)d_in[1];   // [C, N, R] float32
    float* out  = (float*)d_out;
    float* outM = out + 3 * B * K;

    // Bulk zero of M (512 MiB) via driver fill — independent of topk.
    cudaMemsetAsync(outM, 0, (size_t)B * N * N * sizeof(float));
    topk_kernel<<<B, 1024>>>(acc, out);
    finalize_kernel<<<dim3(B, 2), 1024>>>(U, out, outM);
}